// round 2
// baseline (speedup 1.0000x reference)
#include <cuda_runtime.h>

// Problem constants
#define B_ 256
#define H_ 512
#define C_ 64
#define NKNOTS 100
#define KTERMS 8

// GEMM tiling: 32x32 CTA tile, BK=32, 256 threads, 2x2 per-thread tile.
// Grid = (256/32) x (512/32) = 8 x 16 = 128 CTAs, 8 warps/CTA (2 per SMSP).
#define BM 32
#define BN 32
#define BK 32
#define TPB 256

// Scratch (device globals; no allocation allowed)
__device__ float g_x[B_ * C_];
__device__ float g_xdot[B_ * C_];
__device__ float g_relu[B_ * H_];
__device__ float g_drelu[B_ * H_];
__device__ float g_dtanh[B_ * H_];
__device__ float g_u[B_ * H_];
__device__ float g_curr[B_ * H_];
__device__ float g_hdot[B_ * H_];

// ---------------------------------------------------------------------------
// Kernel 1: cubic spline eval at scalar t for x and xdot.
// coeffs layout: [B][N-1][4][C]
// ---------------------------------------------------------------------------
__global__ void spline_kernel(const float* __restrict__ tptr,
                              const float* __restrict__ tobs,
                              const float* __restrict__ coeffs,
                              const float* __restrict__ dcoeffs) {
    __shared__ int s_idx;
    __shared__ float s_dt;
    if (threadIdx.x == 0) {
        float t = tptr[0];
        int cnt = 0;
        for (int i = 0; i < NKNOTS; i++) cnt += (tobs[i] <= t) ? 1 : 0;
        int idx = cnt - 1;                 // searchsorted(side='right') - 1
        idx = max(0, min(idx, NKNOTS - 2));
        s_idx = idx;
        s_dt = t - tobs[idx];
    }
    __syncthreads();
    int gid = blockIdx.x * blockDim.x + threadIdx.x;
    if (gid >= B_ * C_) return;
    int b = gid / C_;
    int c = gid % C_;
    float dt = s_dt;
    size_t base = ((size_t)(b * (NKNOTS - 1) + s_idx)) * 4 * C_ + c;

    float a0 = coeffs[base + 0 * C_];
    float a1 = coeffs[base + 1 * C_];
    float a2 = coeffs[base + 2 * C_];
    float a3 = coeffs[base + 3 * C_];
    g_x[gid] = a0 + dt * (a1 + dt * (a2 + dt * a3));

    a0 = dcoeffs[base + 0 * C_];
    a1 = dcoeffs[base + 1 * C_];
    a2 = dcoeffs[base + 2 * C_];
    a3 = dcoeffs[base + 3 * C_];
    g_xdot[gid] = a0 + dt * (a1 + dt * (a2 + dt * a3));
}

// ---------------------------------------------------------------------------
// Core NT GEMM tile loop: acc[2][2] += A_tile(BMxK) * W_tile(BNxK)^T
// 256 threads: loader covers full 32x32 tile with one float4/thread.
// Inner: thread (ty=tid>>4, tx=tid&15) computes rows ty*2+{0,1}, cols tx*2+{0,1}.
// A-reads broadcast within warp (2 unique float2), B-reads conflict-free.
// ---------------------------------------------------------------------------
__device__ __forceinline__ void gemm_tile_loop(
    const float* __restrict__ A, const float* __restrict__ W, int K,
    float (*As)[BM + 2], float (*Bs)[BN + 2], int tid, float acc[2][2]) {
    const int lrow = tid >> 3;          // 0..31
    const int lk4  = (tid & 7) << 2;    // 0,4,...,28
    const int tm   = (tid >> 4) << 1;   // 0..30
    const int tn   = (tid & 15) << 1;   // 0..30

    float4 pa = *(const float4*)(A + (size_t)lrow * K + lk4);
    float4 pb = *(const float4*)(W + (size_t)lrow * K + lk4);

    const int NT = K / BK;
    for (int t = 0; t < NT; ++t) {
        As[lk4 + 0][lrow] = pa.x; As[lk4 + 1][lrow] = pa.y;
        As[lk4 + 2][lrow] = pa.z; As[lk4 + 3][lrow] = pa.w;
        Bs[lk4 + 0][lrow] = pb.x; Bs[lk4 + 1][lrow] = pb.y;
        Bs[lk4 + 2][lrow] = pb.z; Bs[lk4 + 3][lrow] = pb.w;
        __syncthreads();

        if (t + 1 < NT) {
            int ko = (t + 1) * BK + lk4;
            pa = *(const float4*)(A + (size_t)lrow * K + ko);
            pb = *(const float4*)(W + (size_t)lrow * K + ko);
        }

#pragma unroll
        for (int k = 0; k < BK; ++k) {
            float2 a = *(const float2*)&As[k][tm];
            float2 b = *(const float2*)&Bs[k][tn];
            acc[0][0] = fmaf(a.x, b.x, acc[0][0]);
            acc[0][1] = fmaf(a.x, b.y, acc[0][1]);
            acc[1][0] = fmaf(a.y, b.x, acc[1][0]);
            acc[1][1] = fmaf(a.y, b.y, acc[1][1]);
        }
        __syncthreads();
    }
}

// ---------------------------------------------------------------------------
// Kernel 2: l1 = x@wx^T + h@wh^T + b0 ; wxd = xdot@wx^T
// Writes: g_relu = relu(l1), g_drelu = sigmoid(l1), g_u = drelu * wxd
// ---------------------------------------------------------------------------
__global__ __launch_bounds__(TPB) void gemm_l1(const float* __restrict__ h,
                                               const float* __restrict__ wh,
                                               const float* __restrict__ wx,
                                               const float* __restrict__ b0) {
    __shared__ float As[BK][BM + 2];
    __shared__ float Bs[BK][BN + 2];
    __shared__ float Xs[BK][BM + 2];
    const int tid = threadIdx.x;
    const int bm = blockIdx.x * BM;
    const int bn = blockIdx.y * BN;

    float acc[2][2] = {};
    gemm_tile_loop(h + (size_t)bm * H_, wh + (size_t)bn * H_, H_, As, Bs, tid, acc);

    // wx phase (K = 64): acc += x@wx^T, accw += xdot@wx^T, shared wx tile
    float accw[2][2] = {};
    {
        const int lrow = tid >> 3;
        const int lk4  = (tid & 7) << 2;
        const int tm   = (tid >> 4) << 1;
        const int tn   = (tid & 15) << 1;
        const float* Ax = g_x + (size_t)bm * C_;
        const float* Ad = g_xdot + (size_t)bm * C_;
        const float* Wx = wx + (size_t)bn * C_;
        for (int t = 0; t < C_ / BK; ++t) {
            int ko = t * BK + lk4;
            float4 px = *(const float4*)(Ax + (size_t)lrow * C_ + ko);
            float4 pd = *(const float4*)(Ad + (size_t)lrow * C_ + ko);
            float4 pw = *(const float4*)(Wx + (size_t)lrow * C_ + ko);
            As[lk4 + 0][lrow] = px.x; As[lk4 + 1][lrow] = px.y;
            As[lk4 + 2][lrow] = px.z; As[lk4 + 3][lrow] = px.w;
            Xs[lk4 + 0][lrow] = pd.x; Xs[lk4 + 1][lrow] = pd.y;
            Xs[lk4 + 2][lrow] = pd.z; Xs[lk4 + 3][lrow] = pd.w;
            Bs[lk4 + 0][lrow] = pw.x; Bs[lk4 + 1][lrow] = pw.y;
            Bs[lk4 + 2][lrow] = pw.z; Bs[lk4 + 3][lrow] = pw.w;
            __syncthreads();
#pragma unroll
            for (int k = 0; k < BK; ++k) {
                float2 a = *(const float2*)&As[k][tm];
                float2 x = *(const float2*)&Xs[k][tm];
                float2 b = *(const float2*)&Bs[k][tn];
                acc[0][0] = fmaf(a.x, b.x, acc[0][0]);
                acc[0][1] = fmaf(a.x, b.y, acc[0][1]);
                acc[1][0] = fmaf(a.y, b.x, acc[1][0]);
                acc[1][1] = fmaf(a.y, b.y, acc[1][1]);
                accw[0][0] = fmaf(x.x, b.x, accw[0][0]);
                accw[0][1] = fmaf(x.x, b.y, accw[0][1]);
                accw[1][0] = fmaf(x.y, b.x, accw[1][0]);
                accw[1][1] = fmaf(x.y, b.y, accw[1][1]);
            }
            __syncthreads();
        }
    }

    const int tm = (tid >> 4) << 1;
    const int tn = (tid & 15) << 1;
#pragma unroll
    for (int i = 0; i < 2; ++i) {
#pragma unroll
        for (int j = 0; j < 2; ++j) {
            int row = bm + tm + i;
            int col = bn + tn + j;
            size_t o = (size_t)row * H_ + col;
            float l1 = acc[i][j] + b0[col];
            g_relu[o] = fmaxf(l1, 0.0f);
            float dr = 1.0f / (1.0f + expf(-l1));
            g_drelu[o] = dr;
            g_u[o] = dr * accw[i][j];   // u0 = drelu * (xdot @ wx^T)
        }
    }
}

// ---------------------------------------------------------------------------
// Generic NT GEMM (K = H_) with mode-selected input & epilogue:
//  mode 0: A=g_relu, W=wout -> dtanh = 1 - tanh(acc + b1)^2
//  mode 1: A=g_curr, W=wh   -> g_u = g_drelu * acc
//  mode 2: A=g_u,    W=wout -> v = dtanh*acc; g_curr=v; g_hdot=v        (first)
//  mode 3: A=g_u,    W=wout -> v = dtanh*acc; g_curr=v; g_hdot+=v       (mid)
//  mode 4: A=g_u,    W=wout -> v = dtanh*acc; out = g_hdot + v          (last)
// ---------------------------------------------------------------------------
__global__ __launch_bounds__(TPB) void gemm_nt(const float* __restrict__ W,
                                               const float* __restrict__ bias,
                                               float* __restrict__ out,
                                               int mode) {
    __shared__ float As[BK][BM + 2];
    __shared__ float Bs[BK][BN + 2];
    const int tid = threadIdx.x;
    const int bm = blockIdx.x * BM;
    const int bn = blockIdx.y * BN;

    const float* A = (mode == 0) ? g_relu : (mode == 1) ? g_curr : g_u;

    float acc[2][2] = {};
    gemm_tile_loop(A + (size_t)bm * H_, W + (size_t)bn * H_, H_, As, Bs, tid, acc);

    const int tm = (tid >> 4) << 1;
    const int tn = (tid & 15) << 1;
#pragma unroll
    for (int i = 0; i < 2; ++i) {
#pragma unroll
        for (int j = 0; j < 2; ++j) {
            int row = bm + tm + i;
            int col = bn + tn + j;
            size_t o = (size_t)row * H_ + col;
            float v = acc[i][j];
            if (mode == 0) {
                float th = tanhf(v + bias[col]);
                g_dtanh[o] = 1.0f - th * th;
            } else if (mode == 1) {
                g_u[o] = g_drelu[o] * v;
            } else {
                v *= g_dtanh[o];
                if (mode == 2) {
                    g_curr[o] = v;
                    g_hdot[o] = v;
                } else if (mode == 3) {
                    g_curr[o] = v;
                    g_hdot[o] = g_hdot[o] + v;
                } else {
                    out[o] = g_hdot[o] + v;
                }
            }
        }
    }
}

// ---------------------------------------------------------------------------
extern "C" void kernel_launch(void* const* d_in, const int* in_sizes, int n_in,
                              void* d_out, int out_size) {
    const float* t      = (const float*)d_in[0];
    const float* h      = (const float*)d_in[1];
    const float* coeffs = (const float*)d_in[2];
    const float* dcoeff = (const float*)d_in[3];
    const float* tobs   = (const float*)d_in[4];
    const float* wx     = (const float*)d_in[5];
    const float* wh     = (const float*)d_in[6];
    const float* wout   = (const float*)d_in[7];
    const float* b0     = (const float*)d_in[8];
    const float* b1     = (const float*)d_in[9];
    float* out = (float*)d_out;

    spline_kernel<<<(B_ * C_ + 255) / 256, 256>>>(t, tobs, coeffs, dcoeff);

    dim3 grid(B_ / BM, H_ / BN);  // 8 x 16 = 128 CTAs
    // l1 / relu / drelu / u0
    gemm_l1<<<grid, TPB>>>(h, wh, wx, b0);
    // dtanh from z = relu@wout^T + b1
    gemm_nt<<<grid, TPB>>>(wout, b1, out, 0);
    // curr0 = dtanh * (u0 @ wout^T); hdot = curr0
    gemm_nt<<<grid, TPB>>>(wout, b1, out, 2);
    // 8 von-Neumann iterations: u = drelu*(curr@wh^T); curr = dtanh*(u@wout^T)
    for (int k = 0; k < KTERMS; ++k) {
        gemm_nt<<<grid, TPB>>>(wh, b1, out, 1);
        gemm_nt<<<grid, TPB>>>(wout, b1, out, (k == KTERMS - 1) ? 4 : 3);
    }
}

// round 3
// speedup vs baseline: 1.2587x; 1.2587x over previous
#include <cuda_runtime.h>

// Problem constants
#define B_ 256
#define H_ 512
#define C_ 64
#define NKNOTS 100
#define KTERMS 8

// Persistent GEMM tiling: 32x32 CTA tile, BK=32, 128 threads, per-thread 4x2.
// Grid = (256/32) x (512/32) = 8 x 16 = 128 CTAs (single wave on 148 SMs).
#define BM 32
#define BN 32
#define BK 32
#define TPB 128
#define NCTA 128
#define PAD 36   // smem row stride (floats): 16B-aligned rows

typedef unsigned long long ull;

// Scratch (device globals; no allocation allowed)
__device__ float g_x[B_ * C_];
__device__ float g_xdot[B_ * C_];
__device__ float g_relu[B_ * H_];
__device__ float g_u[B_ * H_];
__device__ float g_curr[B_ * H_];

// grid-wide barrier state (generation scheme; count self-resets)
__device__ unsigned g_bar_count;
__device__ unsigned g_bar_gen;

// ---------------------------------------------------------------------------
// f32x2 packed helpers (sm_100+ dual-fp32; exact fp32 FMA semantics)
// ---------------------------------------------------------------------------
__device__ __forceinline__ ull pk2(float x, float y) {
    ull r; asm("mov.b64 %0, {%1, %2};" : "=l"(r) : "f"(x), "f"(y)); return r;
}
__device__ __forceinline__ float2 upk2(ull v) {
    float2 f; asm("mov.b64 {%0, %1}, %2;" : "=f"(f.x), "=f"(f.y) : "l"(v)); return f;
}
__device__ __forceinline__ void ffma2(ull& d, ull a, ull b) {
    asm("fma.rn.f32x2 %0, %1, %2, %3;" : "=l"(d) : "l"(a), "l"(b), "l"(d));
}

// ---------------------------------------------------------------------------
// Grid-wide barrier. All CTAs resident (128 <= 148 SMs). gen is tracked by
// thread 0 only; initial value read at kernel start is race-free because the
// gen can only advance after every CTA has arrived (hence has read it).
// ---------------------------------------------------------------------------
__device__ __forceinline__ void gbar(unsigned& gen) {
    __syncthreads();
    if (threadIdx.x == 0) {
        __threadfence();
        unsigned old = atomicAdd(&g_bar_count, 1);
        if (old == NCTA - 1) {
            g_bar_count = 0;
            __threadfence();
            atomicAdd(&g_bar_gen, 1);
        } else {
            while (*((volatile unsigned*)&g_bar_gen) == gen) { __nanosleep(32); }
        }
        __threadfence();
        gen++;
    }
    __syncthreads();
}

// ---------------------------------------------------------------------------
// Kernel 1: cubic spline eval at scalar t for x and xdot.
// ---------------------------------------------------------------------------
__global__ void spline_kernel(const float* __restrict__ tptr,
                              const float* __restrict__ tobs,
                              const float* __restrict__ coeffs,
                              const float* __restrict__ dcoeffs) {
    __shared__ int s_idx;
    __shared__ float s_dt;
    if (threadIdx.x == 0) {
        float t = tptr[0];
        int cnt = 0;
        for (int i = 0; i < NKNOTS; i++) cnt += (tobs[i] <= t) ? 1 : 0;
        int idx = cnt - 1;
        idx = max(0, min(idx, NKNOTS - 2));
        s_idx = idx;
        s_dt = t - tobs[idx];
    }
    __syncthreads();
    int gid = blockIdx.x * blockDim.x + threadIdx.x;
    if (gid >= B_ * C_) return;
    int b = gid / C_;
    int c = gid % C_;
    float dt = s_dt;
    size_t base = ((size_t)(b * (NKNOTS - 1) + s_idx)) * 4 * C_ + c;

    float a0 = coeffs[base + 0 * C_], a1 = coeffs[base + 1 * C_];
    float a2 = coeffs[base + 2 * C_], a3 = coeffs[base + 3 * C_];
    g_x[gid] = a0 + dt * (a1 + dt * (a2 + dt * a3));

    a0 = dcoeffs[base + 0 * C_]; a1 = dcoeffs[base + 1 * C_];
    a2 = dcoeffs[base + 2 * C_]; a3 = dcoeffs[base + 3 * C_];
    g_xdot[gid] = a0 + dt * (a1 + dt * (a2 + dt * a3));
}

// ---------------------------------------------------------------------------
// Core NT GEMM: acc += A(BMxK) * W(BNxK)^T for this CTA's 32x32 tile.
// CG: A loaded via ld.global.cg (cross-CTA data; bypass possibly-stale L1).
// DUAL: second A-matrix sharing the same W tile (second accumulator set).
// acc[j][rp] packs output rows (tm+2rp, tm+2rp+1) at column tn+j.
// ---------------------------------------------------------------------------
template <bool CG, bool DUAL>
__device__ __forceinline__ void gemm32(const float* __restrict__ A1,
                                       const float* __restrict__ A2,
                                       const float* __restrict__ W,
                                       int K,
                                       float (*As)[PAD], float (*Xs)[PAD],
                                       float (*Bs)[PAD],
                                       ull acc1[2][2], ull acc2[2][2]) {
    const int tid  = threadIdx.x;
    const int lrow = tid >> 3;          // 0..15
    const int lk4  = (tid & 7) << 2;    // 0,4,...,28
    const int tm   = (tid >> 4) << 2;   // 0,4,...,28
    const int tn   = (tid & 15) << 1;   // 0,2,...,30

    const float* a1p0 = A1 + (size_t)lrow * K + lk4;
    const float* a1p1 = A1 + (size_t)(lrow + 16) * K + lk4;
    const float* a2p0 = A2 + (size_t)lrow * K + lk4;
    const float* a2p1 = A2 + (size_t)(lrow + 16) * K + lk4;
    const float* wp0  = W + (size_t)lrow * K + lk4;
    const float* wp1  = W + (size_t)(lrow + 16) * K + lk4;

    float4 pa0 = CG ? __ldcg((const float4*)a1p0) : *(const float4*)a1p0;
    float4 pa1 = CG ? __ldcg((const float4*)a1p1) : *(const float4*)a1p1;
    float4 px0, px1;
    if (DUAL) {
        px0 = CG ? __ldcg((const float4*)a2p0) : *(const float4*)a2p0;
        px1 = CG ? __ldcg((const float4*)a2p1) : *(const float4*)a2p1;
    }
    float4 pb0 = __ldg((const float4*)wp0);
    float4 pb1 = __ldg((const float4*)wp1);

    const int NT = K / BK;
    for (int t = 0; t < NT; ++t) {
        As[lk4 + 0][lrow]      = pa0.x; As[lk4 + 1][lrow]      = pa0.y;
        As[lk4 + 2][lrow]      = pa0.z; As[lk4 + 3][lrow]      = pa0.w;
        As[lk4 + 0][lrow + 16] = pa1.x; As[lk4 + 1][lrow + 16] = pa1.y;
        As[lk4 + 2][lrow + 16] = pa1.z; As[lk4 + 3][lrow + 16] = pa1.w;
        if (DUAL) {
            Xs[lk4 + 0][lrow]      = px0.x; Xs[lk4 + 1][lrow]      = px0.y;
            Xs[lk4 + 2][lrow]      = px0.z; Xs[lk4 + 3][lrow]      = px0.w;
            Xs[lk4 + 0][lrow + 16] = px1.x; Xs[lk4 + 1][lrow + 16] = px1.y;
            Xs[lk4 + 2][lrow + 16] = px1.z; Xs[lk4 + 3][lrow + 16] = px1.w;
        }
        Bs[lk4 + 0][lrow]      = pb0.x; Bs[lk4 + 1][lrow]      = pb0.y;
        Bs[lk4 + 2][lrow]      = pb0.z; Bs[lk4 + 3][lrow]      = pb0.w;
        Bs[lk4 + 0][lrow + 16] = pb1.x; Bs[lk4 + 1][lrow + 16] = pb1.y;
        Bs[lk4 + 2][lrow + 16] = pb1.z; Bs[lk4 + 3][lrow + 16] = pb1.w;
        __syncthreads();

        if (t + 1 < NT) {
            int ko = (t + 1) * BK;
            pa0 = CG ? __ldcg((const float4*)(a1p0 + ko)) : *(const float4*)(a1p0 + ko);
            pa1 = CG ? __ldcg((const float4*)(a1p1 + ko)) : *(const float4*)(a1p1 + ko);
            if (DUAL) {
                px0 = CG ? __ldcg((const float4*)(a2p0 + ko)) : *(const float4*)(a2p0 + ko);
                px1 = CG ? __ldcg((const float4*)(a2p1 + ko)) : *(const float4*)(a2p1 + ko);
            }
            pb0 = __ldg((const float4*)(wp0 + ko));
            pb1 = __ldg((const float4*)(wp1 + ko));
        }

#pragma unroll
        for (int k = 0; k < BK; ++k) {
            float4 av = *(const float4*)&As[k][tm];
            float2 bv = *(const float2*)&Bs[k][tn];
            ull a01 = pk2(av.x, av.y);
            ull a23 = pk2(av.z, av.w);
            ull bb0 = pk2(bv.x, bv.x);
            ull bb1 = pk2(bv.y, bv.y);
            ffma2(acc1[0][0], a01, bb0);
            ffma2(acc1[0][1], a23, bb0);
            ffma2(acc1[1][0], a01, bb1);
            ffma2(acc1[1][1], a23, bb1);
            if (DUAL) {
                float4 xv = *(const float4*)&Xs[k][tm];
                ull x01 = pk2(xv.x, xv.y);
                ull x23 = pk2(xv.z, xv.w);
                ffma2(acc2[0][0], x01, bb0);
                ffma2(acc2[0][1], x23, bb0);
                ffma2(acc2[1][0], x01, bb1);
                ffma2(acc2[1][1], x23, bb1);
            }
        }
        __syncthreads();
    }
}

// ---------------------------------------------------------------------------
// Persistent fused kernel: whole pipeline after the spline.
// ---------------------------------------------------------------------------
__global__ __launch_bounds__(TPB, 1) void fused_kernel(
    const float* __restrict__ h,  const float* __restrict__ wx,
    const float* __restrict__ wh, const float* __restrict__ wout,
    const float* __restrict__ b0, const float* __restrict__ b1,
    float* __restrict__ out) {
    __shared__ float As[BK][PAD];
    __shared__ float Xs[BK][PAD];
    __shared__ float Bs[BK][PAD];
    __shared__ float sdr[BM][BN + 1];  // drelu tile (local rows x local cols)
    __shared__ float sdt[BM][BN + 1];  // dtanh tile

    const int tid = threadIdx.x;
    const int bm = blockIdx.x * BM;   // batch rows
    const int bn = blockIdx.y * BN;   // H cols
    const int tm = (tid >> 4) << 2;
    const int tn = (tid & 15) << 1;

    unsigned gen = 0;
    if (tid == 0) gen = *((volatile unsigned*)&g_bar_gen);

    const float bc0 = b0[bn + tn], bc1 = b0[bn + tn + 1];
    const float bz0 = b1[bn + tn], bz1 = b1[bn + tn + 1];

    // ---- Phase L1: acc = h@wh^T (+ x@wx^T), accw = xdot@wx^T ----
    ull acc[2][2] = {}, accw[2][2] = {};
    gemm32<false, false>(h + (size_t)bm * H_, nullptr, wh + (size_t)bn * H_,
                         H_, As, Xs, Bs, acc, accw);
    gemm32<false, true>(g_x + (size_t)bm * C_, g_xdot + (size_t)bm * C_,
                        wx + (size_t)bn * C_, C_, As, Xs, Bs, acc, accw);
    // epilogue: relu -> global, drelu -> smem, u0 = drelu * accw -> global
#pragma unroll
    for (int j = 0; j < 2; ++j) {
        float bc = j ? bc1 : bc0;
#pragma unroll
        for (int rp = 0; rp < 2; ++rp) {
            float2 a = upk2(acc[j][rp]);
            float2 w = upk2(accw[j][rp]);
            int r = tm + 2 * rp;
            size_t o = (size_t)(bm + r) * H_ + bn + tn + j;
            float l1a = a.x + bc, l1b = a.y + bc;
            __stcg(&g_relu[o], fmaxf(l1a, 0.0f));
            __stcg(&g_relu[o + H_], fmaxf(l1b, 0.0f));
            float dra = 1.0f / (1.0f + expf(-l1a));
            float drb = 1.0f / (1.0f + expf(-l1b));
            sdr[r][tn + j] = dra;
            sdr[r + 1][tn + j] = drb;
            __stcg(&g_u[o], dra * w.x);
            __stcg(&g_u[o + H_], drb * w.y);
        }
    }
    gbar(gen);

    // ---- Phase D (fused dual): acc1 = relu@wout^T, acc2 = u0@wout^T ----
    ull acc1[2][2] = {}, acc2[2][2] = {};
    gemm32<true, true>(g_relu + (size_t)bm * H_, g_u + (size_t)bm * H_,
                       wout + (size_t)bn * H_, H_, As, Xs, Bs, acc1, acc2);
    float2 hd[2][2];
#pragma unroll
    for (int j = 0; j < 2; ++j) {
        float bz = j ? bz1 : bz0;
#pragma unroll
        for (int rp = 0; rp < 2; ++rp) {
            float2 z = upk2(acc1[j][rp]);
            float2 u = upk2(acc2[j][rp]);
            int r = tm + 2 * rp;
            size_t o = (size_t)(bm + r) * H_ + bn + tn + j;
            float tha = tanhf(z.x + bz), thb = tanhf(z.y + bz);
            float dta = 1.0f - tha * tha, dtb = 1.0f - thb * thb;
            sdt[r][tn + j] = dta;
            sdt[r + 1][tn + j] = dtb;
            float va = dta * u.x, vb = dtb * u.y;
            __stcg(&g_curr[o], va);
            __stcg(&g_curr[o + H_], vb);
            hd[j][rp].x = va;
            hd[j][rp].y = vb;
        }
    }
    gbar(gen);

    // ---- 8 von-Neumann iterations ----
    for (int it = 0; it < KTERMS; ++it) {
        // u = drelu * (curr @ wh^T)
        ull a[2][2] = {};
        gemm32<true, false>(g_curr + (size_t)bm * H_, nullptr,
                            wh + (size_t)bn * H_, H_, As, Xs, Bs, a, acc2);
#pragma unroll
        for (int j = 0; j < 2; ++j) {
#pragma unroll
            for (int rp = 0; rp < 2; ++rp) {
                float2 v = upk2(a[j][rp]);
                int r = tm + 2 * rp;
                size_t o = (size_t)(bm + r) * H_ + bn + tn + j;
                __stcg(&g_u[o], sdr[r][tn + j] * v.x);
                __stcg(&g_u[o + H_], sdr[r + 1][tn + j] * v.y);
            }
        }
        gbar(gen);

        // curr = dtanh * (u @ wout^T); hdot += curr
        ull c[2][2] = {};
        gemm32<true, false>(g_u + (size_t)bm * H_, nullptr,
                            wout + (size_t)bn * H_, H_, As, Xs, Bs, c, acc2);
#pragma unroll
        for (int j = 0; j < 2; ++j) {
#pragma unroll
            for (int rp = 0; rp < 2; ++rp) {
                float2 v = upk2(c[j][rp]);
                int r = tm + 2 * rp;
                size_t o = (size_t)(bm + r) * H_ + bn + tn + j;
                float va = sdt[r][tn + j] * v.x;
                float vb = sdt[r + 1][tn + j] * v.y;
                hd[j][rp].x += va;
                hd[j][rp].y += vb;
                if (it < KTERMS - 1) {
                    __stcg(&g_curr[o], va);
                    __stcg(&g_curr[o + H_], vb);
                }
            }
        }
        if (it < KTERMS - 1) gbar(gen);
    }

    // ---- write h_dot ----
#pragma unroll
    for (int j = 0; j < 2; ++j) {
#pragma unroll
        for (int rp = 0; rp < 2; ++rp) {
            int r = tm + 2 * rp;
            size_t o = (size_t)(bm + r) * H_ + bn + tn + j;
            out[o] = hd[j][rp].x;
            out[o + H_] = hd[j][rp].y;
        }
    }
}

// ---------------------------------------------------------------------------
extern "C" void kernel_launch(void* const* d_in, const int* in_sizes, int n_in,
                              void* d_out, int out_size) {
    const float* t      = (const float*)d_in[0];
    const float* h      = (const float*)d_in[1];
    const float* coeffs = (const float*)d_in[2];
    const float* dcoeff = (const float*)d_in[3];
    const float* tobs   = (const float*)d_in[4];
    const float* wx     = (const float*)d_in[5];
    const float* wh     = (const float*)d_in[6];
    const float* wout   = (const float*)d_in[7];
    const float* b0     = (const float*)d_in[8];
    const float* b1     = (const float*)d_in[9];
    float* out = (float*)d_out;

    spline_kernel<<<(B_ * C_ + 255) / 256, 256>>>(t, tobs, coeffs, dcoeff);

    dim3 grid(B_ / BM, H_ / BN);  // 8 x 16 = 128 CTAs, single wave
    fused_kernel<<<grid, TPB>>>(h, wx, wh, wout, b0, b1, out);
}